// round 2
// baseline (speedup 1.0000x reference)
#include <cuda_runtime.h>
#include <cuda_bf16.h>
#include <math.h>

// Problem constants (fixed by the dataset)
#define B_SZ   512
#define DFEAT  2048
#define DATTR  312
#define NCLS   150

// GEMM tiling
#define BM 64
#define BN 32
#define BK 32
#define SPLITK 8
#define KCHUNK (DFEAT / SPLITK)   // 256

// Scratch (allocation-free: __device__ globals)
__device__ float  g_partial[SPLITK][B_SZ][DATTR];
__device__ double g_S[B_SZ];

// ---------------------------------------------------------------------------
// Kernel 1: pre = x_f @ W  (split-K partials; bias added later)
// grid (10, 8, 8), block 128.  Each thread: 4x4 register tile.
// ---------------------------------------------------------------------------
__global__ __launch_bounds__(128) void gemm_kernel(
    const float* __restrict__ A,   // [512, 2048]
    const float* __restrict__ Wm)  // [2048, 312]
{
    __shared__ float As[BK][BM + 1];  // +1 pad: conflict-free transposed stores
    __shared__ float Bs[BK][BN];

    const int tid = threadIdx.x;
    const int tx  = tid & 7;    // 0..7   -> 4 cols each
    const int ty  = tid >> 3;   // 0..15  -> 4 rows each

    const int colBase = blockIdx.x * BN;
    const int rowBase = blockIdx.y * BM;
    const int kBase0  = blockIdx.z * KCHUNK;

    float acc[4][4] = {};

    const int ar  = tid >> 3;   // 0..15 (row group for A fill)
    const int ac4 = tid & 7;    // 0..7  (float4 col for A fill)

    for (int kt = 0; kt < KCHUNK; kt += BK) {
        const int kBase = kBase0 + kt;

        // Fill A tile (transposed into As[k][m]) — 4 float4 loads per thread
        #pragma unroll
        for (int it = 0; it < 4; it++) {
            const int r = ar + 16 * it;
            const float4 v = *(const float4*)&A[(size_t)(rowBase + r) * DFEAT + kBase + ac4 * 4];
            As[ac4 * 4 + 0][r] = v.x;
            As[ac4 * 4 + 1][r] = v.y;
            As[ac4 * 4 + 2][r] = v.z;
            As[ac4 * 4 + 3][r] = v.w;
        }
        // Fill B tile (natural layout, N-guarded)
        #pragma unroll
        for (int it = 0; it < 8; it++) {
            const int idx = tid + 128 * it;
            const int bk = idx >> 5, bn = idx & 31;
            const int col = colBase + bn;
            Bs[bk][bn] = (col < DATTR) ? Wm[(size_t)(kBase + bk) * DATTR + col] : 0.f;
        }
        __syncthreads();

        #pragma unroll
        for (int k = 0; k < BK; k++) {
            const float a0 = As[k][ty * 4 + 0];
            const float a1 = As[k][ty * 4 + 1];
            const float a2 = As[k][ty * 4 + 2];
            const float a3 = As[k][ty * 4 + 3];
            const float4 bv = *(const float4*)&Bs[k][tx * 4];
            acc[0][0] += a0 * bv.x; acc[0][1] += a0 * bv.y; acc[0][2] += a0 * bv.z; acc[0][3] += a0 * bv.w;
            acc[1][0] += a1 * bv.x; acc[1][1] += a1 * bv.y; acc[1][2] += a1 * bv.z; acc[1][3] += a1 * bv.w;
            acc[2][0] += a2 * bv.x; acc[2][1] += a2 * bv.y; acc[2][2] += a2 * bv.z; acc[2][3] += a2 * bv.w;
            acc[3][0] += a3 * bv.x; acc[3][1] += a3 * bv.y; acc[3][2] += a3 * bv.z; acc[3][3] += a3 * bv.w;
        }
        __syncthreads();
    }

    #pragma unroll
    for (int i = 0; i < 4; i++) {
        const int row = rowBase + ty * 4 + i;
        #pragma unroll
        for (int j = 0; j < 4; j++) {
            const int col = colBase + tx * 4 + j;
            if (col < DATTR) g_partial[blockIdx.z][row][col] = acc[i][j];
        }
    }
}

// ---------------------------------------------------------------------------
// Kernel 2: per-row S[i] = rowsum(pre_i) - DATTR * logsumexp(pre_i)
// grid 512, block 128. Double accumulation for numerical safety.
// ---------------------------------------------------------------------------
__global__ __launch_bounds__(128) void rowstats_kernel(const float* __restrict__ bvec)
{
    const int i   = blockIdx.x;
    const int tid = threadIdx.x;

    __shared__ float  vals[DATTR];
    __shared__ float  smax[4];
    __shared__ double sse[4];
    __shared__ double srs[4];

    for (int c = tid; c < DATTR; c += 128) {
        float v = bvec[c];
        #pragma unroll
        for (int s = 0; s < SPLITK; s++) v += g_partial[s][i][c];
        vals[c] = v;
    }
    __syncthreads();

    // row max
    float m = -1e30f;
    for (int c = tid; c < DATTR; c += 128) m = fmaxf(m, vals[c]);
    #pragma unroll
    for (int o = 16; o; o >>= 1) m = fmaxf(m, __shfl_xor_sync(0xffffffffu, m, o));
    if ((tid & 31) == 0) smax[tid >> 5] = m;
    __syncthreads();
    m = fmaxf(fmaxf(smax[0], smax[1]), fmaxf(smax[2], smax[3]));

    // sumexp + rowsum (double)
    double se = 0.0, rs = 0.0;
    for (int c = tid; c < DATTR; c += 128) {
        const double v = (double)vals[c];
        se += exp(v - (double)m);
        rs += v;
    }
    #pragma unroll
    for (int o = 16; o; o >>= 1) {
        se += __shfl_xor_sync(0xffffffffu, se, o);
        rs += __shfl_xor_sync(0xffffffffu, rs, o);
    }
    if ((tid & 31) == 0) { sse[tid >> 5] = se; srs[tid >> 5] = rs; }
    __syncthreads();

    if (tid == 0) {
        const double seT = sse[0] + sse[1] + sse[2] + sse[3];
        const double rsT = srs[0] + srs[1] + srs[2] + srs[3];
        const double lse = (double)m + log(seT);
        g_S[i] = rsT - (double)DATTR * lse;
    }
}

// ---------------------------------------------------------------------------
// Kernel 3: loss = mean over same-label upper pairs of (S_j - S_i)
// single block, 512 threads (thread t owns row i = t).
//
// Label dtype sniff: JAX with default x64-disabled emits int32 labels even
// though the reference asks for int64. Labels lie in [0, 150), so if the
// buffer is really int64, every odd 32-bit word is zero. We test the first
// 256 odd words (in-bounds for BOTH layouts: int32 buffer has 512 words).
// Probability of a false int64 detection with real int32 labels ~ (1/150)^256.
// ---------------------------------------------------------------------------
__global__ __launch_bounds__(512) void pair_loss_kernel(
    const int* __restrict__ labw, float* __restrict__ out)
{
    __shared__ int           slab[B_SZ];
    __shared__ int           s_not64;
    __shared__ double        sS[B_SZ];
    __shared__ double        swsum[16];
    __shared__ unsigned int  swcnt[16];

    const int t = threadIdx.x;
    if (t == 0) s_not64 = 0;
    __syncthreads();

    if (t < 256 && labw[2 * t + 1] != 0) atomicOr(&s_not64, 1);
    __syncthreads();

    const bool is64 = (s_not64 == 0);
    slab[t] = is64 ? labw[2 * t] : labw[t];
    sS[t]   = g_S[t];
    __syncthreads();

    const int    li = slab[t];
    const double Si = sS[t];
    double       local = 0.0;
    unsigned int cnt   = 0;

    for (int j = t + 1; j < B_SZ; j++) {
        if (slab[j] == li) { local += sS[j] - Si; cnt++; }
    }

    #pragma unroll
    for (int o = 16; o; o >>= 1) {
        local += __shfl_xor_sync(0xffffffffu, local, o);
        cnt   += __shfl_xor_sync(0xffffffffu, cnt, o);
    }
    if ((t & 31) == 0) { swsum[t >> 5] = local; swcnt[t >> 5] = cnt; }
    __syncthreads();

    if (t == 0) {
        double s = 0.0; unsigned int c = 0;
        #pragma unroll
        for (int w = 0; w < 16; w++) { s += swsum[w]; c += swcnt[w]; }
        out[0] = (float)((c > 0) ? (s / (double)c) : s);
    }
}

// ---------------------------------------------------------------------------
extern "C" void kernel_launch(void* const* d_in, const int* in_sizes, int n_in,
                              void* d_out, int out_size)
{
    const float* x   = (const float*)d_in[0];      // [512, 2048]
    const float* Wm  = (const float*)d_in[1];      // [2048, 312]
    const float* b   = (const float*)d_in[2];      // [312]
    // d_in[3] = seen_att : unused (cancels exactly for same-label pairs)
    const int*   lab = (const int*)d_in[4];        // [512] int32 (or int64 words)

    dim3 grid1((DATTR + BN - 1) / BN, B_SZ / BM, SPLITK);  // (10, 8, 8)
    gemm_kernel<<<grid1, 128>>>(x, Wm);
    rowstats_kernel<<<B_SZ, 128>>>(b);
    pair_loss_kernel<<<1, B_SZ>>>(lab, (float*)d_out);
}

// round 3
// speedup vs baseline: 3.2290x; 3.2290x over previous
#include <cuda_runtime.h>
#include <cuda_bf16.h>
#include <math.h>

// Problem constants (fixed by the dataset)
#define B_SZ   512
#define DFEAT  2048
#define DATTR  312
#define NCLS   150

// GEMM tiling
#define BM 64
#define BN 32
#define BK 32
#define SPLITK 8
#define KCHUNK (DFEAT / SPLITK)   // 256

// Scratch (allocation-free: __device__ globals)
__device__ float g_partial[SPLITK][B_SZ][DATTR];
__device__ float g_Sf[B_SZ];

// ---------------------------------------------------------------------------
// Kernel 1: pre = x_f @ W  (split-K partials; bias added later)
// grid (10, 8, 8), block 128.  Each thread: 4x4 register tile.
// ---------------------------------------------------------------------------
__global__ __launch_bounds__(128) void gemm_kernel(
    const float* __restrict__ A,   // [512, 2048]
    const float* __restrict__ Wm)  // [2048, 312]
{
    __shared__ float As[BK][BM + 1];  // +1 pad: conflict-free transposed stores
    __shared__ float Bs[BK][BN];

    const int tid = threadIdx.x;
    const int tx  = tid & 7;    // 0..7   -> 4 cols each
    const int ty  = tid >> 3;   // 0..15  -> 4 rows each

    const int colBase = blockIdx.x * BN;
    const int rowBase = blockIdx.y * BM;
    const int kBase0  = blockIdx.z * KCHUNK;

    float acc[4][4] = {};

    const int ar  = tid >> 3;   // 0..15 (row group for A fill)
    const int ac4 = tid & 7;    // 0..7  (float4 col for A fill)

    for (int kt = 0; kt < KCHUNK; kt += BK) {
        const int kBase = kBase0 + kt;

        // Fill A tile (transposed into As[k][m]) — 4 float4 loads per thread
        #pragma unroll
        for (int it = 0; it < 4; it++) {
            const int r = ar + 16 * it;
            const float4 v = *(const float4*)&A[(size_t)(rowBase + r) * DFEAT + kBase + ac4 * 4];
            As[ac4 * 4 + 0][r] = v.x;
            As[ac4 * 4 + 1][r] = v.y;
            As[ac4 * 4 + 2][r] = v.z;
            As[ac4 * 4 + 3][r] = v.w;
        }
        // Fill B tile (natural layout, N-guarded)
        #pragma unroll
        for (int it = 0; it < 8; it++) {
            const int idx = tid + 128 * it;
            const int bk = idx >> 5, bn = idx & 31;
            const int col = colBase + bn;
            Bs[bk][bn] = (col < DATTR) ? Wm[(size_t)(kBase + bk) * DATTR + col] : 0.f;
        }
        __syncthreads();

        #pragma unroll
        for (int k = 0; k < BK; k++) {
            const float a0 = As[k][ty * 4 + 0];
            const float a1 = As[k][ty * 4 + 1];
            const float a2 = As[k][ty * 4 + 2];
            const float a3 = As[k][ty * 4 + 3];
            const float4 bv = *(const float4*)&Bs[k][tx * 4];
            acc[0][0] += a0 * bv.x; acc[0][1] += a0 * bv.y; acc[0][2] += a0 * bv.z; acc[0][3] += a0 * bv.w;
            acc[1][0] += a1 * bv.x; acc[1][1] += a1 * bv.y; acc[1][2] += a1 * bv.z; acc[1][3] += a1 * bv.w;
            acc[2][0] += a2 * bv.x; acc[2][1] += a2 * bv.y; acc[2][2] += a2 * bv.z; acc[2][3] += a2 * bv.w;
            acc[3][0] += a3 * bv.x; acc[3][1] += a3 * bv.y; acc[3][2] += a3 * bv.z; acc[3][3] += a3 * bv.w;
        }
        __syncthreads();
    }

    #pragma unroll
    for (int i = 0; i < 4; i++) {
        const int row = rowBase + ty * 4 + i;
        #pragma unroll
        for (int j = 0; j < 4; j++) {
            const int col = colBase + tx * 4 + j;
            if (col < DATTR) g_partial[blockIdx.z][row][col] = acc[i][j];
        }
    }
}

// ---------------------------------------------------------------------------
// Kernel 2: per-row S[i] = rowsum(pre_i) - DATTR * logsumexp(pre_i)
// grid 512, block 128. All-fp32: the reference itself is fp32 JAX.
// ---------------------------------------------------------------------------
__global__ __launch_bounds__(128) void rowstats_kernel(const float* __restrict__ bvec)
{
    const int i   = blockIdx.x;
    const int tid = threadIdx.x;

    __shared__ float vals[DATTR];
    __shared__ float smax[4];
    __shared__ float sse[4];
    __shared__ float srs[4];

    for (int c = tid; c < DATTR; c += 128) {
        float v = bvec[c];
        #pragma unroll
        for (int s = 0; s < SPLITK; s++) v += g_partial[s][i][c];
        vals[c] = v;
    }
    __syncthreads();

    // row max
    float m = -1e30f;
    for (int c = tid; c < DATTR; c += 128) m = fmaxf(m, vals[c]);
    #pragma unroll
    for (int o = 16; o; o >>= 1) m = fmaxf(m, __shfl_xor_sync(0xffffffffu, m, o));
    if ((tid & 31) == 0) smax[tid >> 5] = m;
    __syncthreads();
    m = fmaxf(fmaxf(smax[0], smax[1]), fmaxf(smax[2], smax[3]));

    // sumexp + rowsum (fp32)
    float se = 0.f, rs = 0.f;
    for (int c = tid; c < DATTR; c += 128) {
        const float v = vals[c];
        se += expf(v - m);
        rs += v;
    }
    #pragma unroll
    for (int o = 16; o; o >>= 1) {
        se += __shfl_xor_sync(0xffffffffu, se, o);
        rs += __shfl_xor_sync(0xffffffffu, rs, o);
    }
    if ((tid & 31) == 0) { sse[tid >> 5] = se; srs[tid >> 5] = rs; }
    __syncthreads();

    if (tid == 0) {
        const float seT = sse[0] + sse[1] + sse[2] + sse[3];
        const float rsT = srs[0] + srs[1] + srs[2] + srs[3];
        const float lse = m + logf(seT);
        g_Sf[i] = rsT - (float)DATTR * lse;
    }
}

// ---------------------------------------------------------------------------
// Kernel 3: loss = mean over same-label upper pairs of (S_j - S_i)
// single block, 512 threads (thread t owns row i = t).
//
// Label dtype sniff: JAX with default x64-disabled emits int32 labels even
// though the reference asks for int64. Labels lie in [0, 150), so if the
// buffer is really int64, every odd 32-bit word is zero. We test the first
// 256 odd words (in-bounds for BOTH layouts: int32 buffer has 512 words).
// ---------------------------------------------------------------------------
__global__ __launch_bounds__(512) void pair_loss_kernel(
    const int* __restrict__ labw, float* __restrict__ out)
{
    __shared__ int           slab[B_SZ];
    __shared__ int           s_not64;
    __shared__ float         sS[B_SZ];
    __shared__ float         swsum[16];
    __shared__ unsigned int  swcnt[16];

    const int t = threadIdx.x;
    if (t == 0) s_not64 = 0;
    __syncthreads();

    if (t < 256 && labw[2 * t + 1] != 0) atomicOr(&s_not64, 1);
    __syncthreads();

    const bool is64 = (s_not64 == 0);
    slab[t] = is64 ? labw[2 * t] : labw[t];
    sS[t]   = g_Sf[t];
    __syncthreads();

    const int   li = slab[t];
    const float Si = sS[t];
    float        local = 0.f;
    unsigned int cnt   = 0;

    for (int j = t + 1; j < B_SZ; j++) {
        if (slab[j] == li) { local += sS[j] - Si; cnt++; }
    }

    #pragma unroll
    for (int o = 16; o; o >>= 1) {
        local += __shfl_xor_sync(0xffffffffu, local, o);
        cnt   += __shfl_xor_sync(0xffffffffu, cnt, o);
    }
    if ((t & 31) == 0) { swsum[t >> 5] = local; swcnt[t >> 5] = cnt; }
    __syncthreads();

    if (t == 0) {
        float s = 0.f; unsigned int c = 0;
        #pragma unroll
        for (int w = 0; w < 16; w++) { s += swsum[w]; c += swcnt[w]; }
        out[0] = (c > 0) ? (s / (float)c) : s;
    }
}

// ---------------------------------------------------------------------------
extern "C" void kernel_launch(void* const* d_in, const int* in_sizes, int n_in,
                              void* d_out, int out_size)
{
    const float* x   = (const float*)d_in[0];      // [512, 2048]
    const float* Wm  = (const float*)d_in[1];      // [2048, 312]
    const float* b   = (const float*)d_in[2];      // [312]
    // d_in[3] = seen_att : unused (cancels exactly for same-label pairs)
    const int*   lab = (const int*)d_in[4];        // [512] int32 (or int64 words)

    dim3 grid1((DATTR + BN - 1) / BN, B_SZ / BM, SPLITK);  // (10, 8, 8)
    gemm_kernel<<<grid1, 128>>>(x, Wm);
    rowstats_kernel<<<B_SZ, 128>>>(b);
    pair_loss_kernel<<<1, B_SZ>>>(lab, (float*)d_out);
}